// round 3
// baseline (speedup 1.0000x reference)
#include <cuda_runtime.h>
#include <math.h>

#define NMAX   2048
#define CB     32          // column blocks of 64 -> supports up to 2048 boxes
#define TPB    64
#define FEPS   1e-8f
#define THRESH 0.7f

// scratch (device globals: no allocation allowed)
__device__ float g_px[NMAX * 4];
__device__ float g_py[NMAX * 4];
__device__ float g_area[NMAX];
__device__ float g_cx[NMAX];
__device__ float g_cy[NMAX];
__device__ float g_r[NMAX];
__device__ unsigned long long g_mask[NMAX * CB];

__device__ __forceinline__ float cross2(float ax, float ay, float bx, float by) {
    return ax * by - ay * bx;
}

// ---------------------------------------------------------------------------
// Kernel 1: corners + per-box metadata
// ---------------------------------------------------------------------------
__global__ void corners_kernel(const float* __restrict__ boxes, int n) {
    int i = blockIdx.x * blockDim.x + threadIdx.x;
    if (i >= n) return;
    float xc = boxes[i * 5 + 0];
    float yc = boxes[i * 5 + 1];
    float w  = boxes[i * 5 + 2];
    float h  = boxes[i * 5 + 3];
    float t  = boxes[i * 5 + 4];
    float th = t * (float)(M_PI / 180.0);
    float c = cosf(th), s = sinf(th);
    const float lx[4] = {0.5f, -0.5f, -0.5f, 0.5f};
    const float ly[4] = {0.5f, 0.5f, -0.5f, -0.5f};
#pragma unroll
    for (int k = 0; k < 4; k++) {
        g_px[i * 4 + k] = xc + lx[k] * w * c - ly[k] * h * s;
        g_py[i * 4 + k] = yc + lx[k] * w * s + ly[k] * h * c;
    }
    g_area[i] = w * h;
    g_cx[i] = xc;
    g_cy[i] = yc;
    g_r[i]  = 0.5f * sqrtf(w * w + h * h);
}

// ---------------------------------------------------------------------------
// Exact replica of the reference _pair_inter_area (compacted form).
// Candidate order (edge intersections k-major, then c1 verts, then c2 verts)
// matches the reference concatenation order; insertion sort is stable like
// jnp.argsort, so tie handling matches.
// ---------------------------------------------------------------------------
__device__ float pair_inter(const float* __restrict__ px, const float* __restrict__ py,
                            const float* __restrict__ qx, const float* __restrict__ qy) {
    float d1x[4], d1y[4], d2x[4], d2y[4];
#pragma unroll
    for (int k = 0; k < 4; k++) {
        int k1 = (k + 1) & 3;
        d1x[k] = px[k1] - px[k]; d1y[k] = py[k1] - py[k];
        d2x[k] = qx[k1] - qx[k]; d2y[k] = qy[k1] - qy[k];
    }
    float X[24], Y[24];
    int m = 0;
    // edge-edge intersections (16 candidates)
#pragma unroll
    for (int k = 0; k < 4; k++) {
#pragma unroll
        for (int l = 0; l < 4; l++) {
            float den = cross2(d1x[k], d1y[k], d2x[l], d2y[l]);
            if (fabsf(den) > FEPS) {
                float rx = qx[l] - px[k], ry = qy[l] - py[k];
                float t = cross2(rx, ry, d2x[l], d2y[l]) / den;
                float u = cross2(rx, ry, d1x[k], d1y[k]) / den;
                if (t >= 0.f && t <= 1.f && u >= 0.f && u <= 1.f) {
                    X[m] = px[k] + t * d1x[k];
                    Y[m] = py[k] + t * d1y[k];
                    m++;
                }
            }
        }
    }
    // c1 vertices inside c2
#pragma unroll
    for (int k = 0; k < 4; k++) {
        bool pos = true, neg = true;
#pragma unroll
        for (int l = 0; l < 4; l++) {
            float cr = cross2(d2x[l], d2y[l], px[k] - qx[l], py[k] - qy[l]);
            pos = pos && (cr >= -FEPS);
            neg = neg && (cr <= FEPS);
        }
        if (pos || neg) { X[m] = px[k]; Y[m] = py[k]; m++; }
    }
    // c2 vertices inside c1
#pragma unroll
    for (int k = 0; k < 4; k++) {
        bool pos = true, neg = true;
#pragma unroll
        for (int l = 0; l < 4; l++) {
            float cr = cross2(d1x[l], d1y[l], qx[k] - px[l], qy[k] - py[l]);
            pos = pos && (cr >= -FEPS);
            neg = neg && (cr <= FEPS);
        }
        if (pos || neg) { X[m] = qx[k]; Y[m] = qy[k]; m++; }
    }
    if (m < 3) return 0.f;

    float cx = 0.f, cy = 0.f;
    for (int i = 0; i < m; i++) { cx += X[i]; cy += Y[i]; }
    float inv = 1.f / (float)m;
    cx *= inv; cy *= inv;

    float ang[24];
    for (int i = 0; i < m; i++) ang[i] = atan2f(Y[i] - cy, X[i] - cx);

    // stable insertion sort by angle
    for (int i = 1; i < m; i++) {
        float a = ang[i], x = X[i], y = Y[i];
        int j = i - 1;
        while (j >= 0 && ang[j] > a) {
            ang[j + 1] = ang[j]; X[j + 1] = X[j]; Y[j + 1] = Y[j];
            j--;
        }
        ang[j + 1] = a; X[j + 1] = x; Y[j + 1] = y;
    }

    float area = 0.f;
    for (int i = 0; i < m; i++) {
        int j = (i + 1 == m) ? 0 : i + 1;
        area += cross2(X[i] - cx, Y[i] - cy, X[j] - cx, Y[j] - cy);
    }
    return 0.5f * fabsf(area);
}

// ---------------------------------------------------------------------------
// Kernel 2: suppression-mask tiles (torchvision-style 64x64 bit tiles)
// ---------------------------------------------------------------------------
__global__ void mask_kernel(int n) {
    const int colb = blockIdx.x;
    const int rowb = blockIdx.y;

    __shared__ float sqx[TPB * 4], sqy[TPB * 4];
    __shared__ float sarea[TPB], scx[TPB], scy[TPB], sr[TPB];

    const int col0 = colb * TPB;
    const int colsz = min(TPB, n - col0);

    if (colb >= rowb) {
        int t = threadIdx.x;
        if (t < colsz) {
            int j = col0 + t;
#pragma unroll
            for (int k = 0; k < 4; k++) {
                sqx[t * 4 + k] = g_px[j * 4 + k];
                sqy[t * 4 + k] = g_py[j * 4 + k];
            }
            sarea[t] = g_area[j];
            scx[t] = g_cx[j];
            scy[t] = g_cy[j];
            sr[t]  = g_r[j];
        }
    }
    __syncthreads();

    const int row = rowb * TPB + threadIdx.x;
    if (row >= n) return;
    if (colb < rowb) { g_mask[row * CB + colb] = 0ULL; return; }

    float p1x[4], p1y[4];
#pragma unroll
    for (int k = 0; k < 4; k++) {
        p1x[k] = g_px[row * 4 + k];
        p1y[k] = g_py[row * 4 + k];
    }
    const float ai = g_area[row];
    const float cxi = g_cx[row], cyi = g_cy[row], ri = g_r[row];

    unsigned long long bits = 0ULL;
    const int start = (colb == rowb) ? (threadIdx.x + 1) : 0;
    for (int jj = start; jj < colsz; jj++) {
        float aj = sarea[jj];
        // exact-safe reject 1: IoU <= min/max area ratio
        float amin = fminf(ai, aj), amax = fmaxf(ai, aj);
        if (amin <= THRESH * amax) continue;
        // exact-safe reject 2: bounding circles disjoint -> intersection = 0
        float dx = cxi - scx[jj], dy = cyi - scy[jj];
        float rr = ri + sr[jj];
        if (dx * dx + dy * dy >= rr * rr) continue;

        float inter = pair_inter(p1x, p1y, &sqx[jj * 4], &sqy[jj * 4]);
        float uni = ai + aj - inter;
        float iou = inter / fmaxf(uni, FEPS);
        if (iou > THRESH) bits |= (1ULL << jj);
    }
    g_mask[row * CB + colb] = bits;
}

// ---------------------------------------------------------------------------
// Kernel 3: serial greedy reduce (1 warp; lane owns one 64-bit remv word).
// One-row prefetch hides the L2 latency of the mask row load.
// OUTPUT IS float32 (the harness's __output__ dtype): indices as floats,
// padded with -1.0f. Ints < 2^24 are exact in f32.
// ---------------------------------------------------------------------------
__global__ void reduce_kernel(int n, float* __restrict__ out, int out_size) {
    const int lane = threadIdx.x;  // 32 lanes
    unsigned long long remv = 0ULL;
    unsigned long long cur = g_mask[lane];  // row 0 prefetch
    int num = 0;
    for (int i = 0; i < n; i++) {
        unsigned long long nxt = (i + 1 < n) ? g_mask[(size_t)(i + 1) * CB + lane] : 0ULL;
        int b = i >> 6;
        unsigned long long w = __shfl_sync(0xffffffffu, remv, b);
        if (!((w >> (i & 63)) & 1ULL)) {
            if (lane == 0 && num < out_size) out[num] = (float)i;
            num++;
            remv |= cur;
        }
        cur = nxt;
    }
    if (lane == 0) {
        for (int k = num; k < out_size; k++) out[k] = -1.0f;
    }
}

// ---------------------------------------------------------------------------
extern "C" void kernel_launch(void* const* d_in, const int* in_sizes, int n_in,
                              void* d_out, int out_size) {
    const float* boxes = (const float*)d_in[0];
    int n = in_sizes[0] / 5;

    corners_kernel<<<(n + 127) / 128, 128>>>(boxes, n);

    int rb = (n + TPB - 1) / TPB;  // 32 for n=2000
    dim3 grid(rb, rb);
    mask_kernel<<<grid, TPB>>>(n);

    reduce_kernel<<<1, 32>>>(n, (float*)d_out, out_size);
}

// round 4
// speedup vs baseline: 1.2759x; 1.2759x over previous
#include <cuda_runtime.h>
#include <math.h>

#define NMAX   2048
#define CB     32          // column blocks of 64 -> supports up to 2048 boxes
#define TPB    64
#define FEPS   1e-8f
#define THRESH 0.7f
#define CAP    (NMAX * NMAX / 2)   // worklist capacity (worst case), 8MB

// scratch (device globals: no allocation allowed)
__device__ float g_px[NMAX * 4];
__device__ float g_py[NMAX * 4];
__device__ float g_area[NMAX];
__device__ float g_cx[NMAX];
__device__ float g_cy[NMAX];
__device__ float g_r[NMAX];
__device__ unsigned long long g_mask[NMAX * CB];
__device__ unsigned int g_work[CAP];   // packed pairs: (i << 11) | j
__device__ int g_count;

__device__ __forceinline__ float cross2(float ax, float ay, float bx, float by) {
    return ax * by - ay * bx;
}

// ---------------------------------------------------------------------------
// Kernel 1: corners + per-box metadata (+ zero worklist counter)
// ---------------------------------------------------------------------------
__global__ void corners_kernel(const float* __restrict__ boxes, int n) {
    int i = blockIdx.x * blockDim.x + threadIdx.x;
    if (i == 0) g_count = 0;
    if (i >= n) return;
    float xc = boxes[i * 5 + 0];
    float yc = boxes[i * 5 + 1];
    float w  = boxes[i * 5 + 2];
    float h  = boxes[i * 5 + 3];
    float t  = boxes[i * 5 + 4];
    float th = t * (float)(M_PI / 180.0);
    float c = cosf(th), s = sinf(th);
    const float lx[4] = {0.5f, -0.5f, -0.5f, 0.5f};
    const float ly[4] = {0.5f, 0.5f, -0.5f, -0.5f};
#pragma unroll
    for (int k = 0; k < 4; k++) {
        g_px[i * 4 + k] = xc + lx[k] * w * c - ly[k] * h * s;
        g_py[i * 4 + k] = yc + lx[k] * w * s + ly[k] * h * c;
    }
    g_area[i] = w * h;
    g_cx[i] = xc;
    g_cy[i] = yc;
    g_r[i]  = 0.5f * sqrtf(w * w + h * h);
}

// ---------------------------------------------------------------------------
// Kernel 2: cheap exact-safe filters over all upper-triangle pairs.
// Survivors are pushed (warp-aggregated) into g_work. Also zeroes g_mask.
// Control flow is kept warp-uniform so __ballot_sync is safe: the diagonal
// start offset and row validity are folded into the `hit` predicate.
// ---------------------------------------------------------------------------
__global__ void filter_kernel(int n) {
    const int colb = blockIdx.x;
    const int rowb = blockIdx.y;
    const int row = rowb * TPB + threadIdx.x;

    // zero this row's mask word for this column block
    if (row < n) g_mask[(size_t)row * CB + colb] = 0ULL;
    if (colb < rowb) return;   // uniform per block

    __shared__ float sarea[TPB], scx[TPB], scy[TPB], sr[TPB];
    const int col0 = colb * TPB;
    {
        int t = threadIdx.x;
        int j = col0 + t;
        if (j < n) {
            sarea[t] = g_area[j];
            scx[t] = g_cx[j];
            scy[t] = g_cy[j];
            sr[t]  = g_r[j];
        }
    }
    __syncthreads();

    const int colsz = min(TPB, n - col0);
    const bool rowvalid = (row < n);
    const int rload = rowvalid ? row : (n - 1);
    const float ai  = g_area[rload];
    const float cxi = g_cx[rload], cyi = g_cy[rload], ri = g_r[rload];
    const bool diag = (colb == rowb);
    const int lane = threadIdx.x & 31;

    for (int jj = 0; jj < colsz; jj++) {
        bool hit = rowvalid && (!diag || jj > threadIdx.x);
        if (hit) {
            float aj = sarea[jj];
            float amin = fminf(ai, aj), amax = fmaxf(ai, aj);
            float dx = cxi - scx[jj], dy = cyi - scy[jj];
            float rr = ri + sr[jj];
            hit = (amin > THRESH * amax) && (dx * dx + dy * dy < rr * rr);
        }
        unsigned b = __ballot_sync(0xffffffffu, hit);
        if (b) {
            int leader = __ffs(b) - 1;
            int base = 0;
            if (lane == leader) base = atomicAdd(&g_count, __popc(b));
            base = __shfl_sync(0xffffffffu, base, leader);
            if (hit) {
                int idx = base + __popc(b & ((1u << lane) - 1u));
                if (idx < CAP)
                    g_work[idx] = ((unsigned)row << 11) | (unsigned)(col0 + jj);
            }
        }
    }
}

// ---------------------------------------------------------------------------
// Exact replica of the reference _pair_inter_area (compacted form).
// Candidate order (edge intersections k-major, then c1 verts, then c2 verts)
// matches the reference concatenation order; insertion sort is stable like
// jnp.argsort, so tie handling matches.
// ---------------------------------------------------------------------------
__device__ float pair_inter(const float* __restrict__ px, const float* __restrict__ py,
                            const float* __restrict__ qx, const float* __restrict__ qy) {
    float d1x[4], d1y[4], d2x[4], d2y[4];
#pragma unroll
    for (int k = 0; k < 4; k++) {
        int k1 = (k + 1) & 3;
        d1x[k] = px[k1] - px[k]; d1y[k] = py[k1] - py[k];
        d2x[k] = qx[k1] - qx[k]; d2y[k] = qy[k1] - qy[k];
    }
    float X[24], Y[24];
    int m = 0;
    // edge-edge intersections (16 candidates)
#pragma unroll
    for (int k = 0; k < 4; k++) {
#pragma unroll
        for (int l = 0; l < 4; l++) {
            float den = cross2(d1x[k], d1y[k], d2x[l], d2y[l]);
            if (fabsf(den) > FEPS) {
                float rx = qx[l] - px[k], ry = qy[l] - py[k];
                float t = cross2(rx, ry, d2x[l], d2y[l]) / den;
                float u = cross2(rx, ry, d1x[k], d1y[k]) / den;
                if (t >= 0.f && t <= 1.f && u >= 0.f && u <= 1.f) {
                    X[m] = px[k] + t * d1x[k];
                    Y[m] = py[k] + t * d1y[k];
                    m++;
                }
            }
        }
    }
    // c1 vertices inside c2
#pragma unroll
    for (int k = 0; k < 4; k++) {
        bool pos = true, neg = true;
#pragma unroll
        for (int l = 0; l < 4; l++) {
            float cr = cross2(d2x[l], d2y[l], px[k] - qx[l], py[k] - qy[l]);
            pos = pos && (cr >= -FEPS);
            neg = neg && (cr <= FEPS);
        }
        if (pos || neg) { X[m] = px[k]; Y[m] = py[k]; m++; }
    }
    // c2 vertices inside c1
#pragma unroll
    for (int k = 0; k < 4; k++) {
        bool pos = true, neg = true;
#pragma unroll
        for (int l = 0; l < 4; l++) {
            float cr = cross2(d1x[l], d1y[l], qx[k] - px[l], qy[k] - py[l]);
            pos = pos && (cr >= -FEPS);
            neg = neg && (cr <= FEPS);
        }
        if (pos || neg) { X[m] = qx[k]; Y[m] = qy[k]; m++; }
    }
    if (m < 3) return 0.f;

    float cx = 0.f, cy = 0.f;
    for (int i = 0; i < m; i++) { cx += X[i]; cy += Y[i]; }
    float inv = 1.f / (float)m;
    cx *= inv; cy *= inv;

    float ang[24];
    for (int i = 0; i < m; i++) ang[i] = atan2f(Y[i] - cy, X[i] - cx);

    // stable insertion sort by angle
    for (int i = 1; i < m; i++) {
        float a = ang[i], x = X[i], y = Y[i];
        int j = i - 1;
        while (j >= 0 && ang[j] > a) {
            ang[j + 1] = ang[j]; X[j + 1] = X[j]; Y[j + 1] = Y[j];
            j--;
        }
        ang[j + 1] = a; X[j + 1] = x; Y[j + 1] = y;
    }

    float area = 0.f;
    for (int i = 0; i < m; i++) {
        int j = (i + 1 == m) ? 0 : i + 1;
        area += cross2(X[i] - cx, Y[i] - cy, X[j] - cx, Y[j] - cy);
    }
    return 0.5f * fabsf(area);
}

// ---------------------------------------------------------------------------
// Kernel 3: exact clip, one thread per surviving pair (grid-stride).
// No divergence amplification: every active thread runs the heavy path.
// atomicOr is commutative -> deterministic mask regardless of ordering.
// ---------------------------------------------------------------------------
__global__ void clip_kernel() {
    int cnt = g_count;
    if (cnt > CAP) cnt = CAP;
    const int stride = gridDim.x * blockDim.x;
    for (int k = blockIdx.x * blockDim.x + threadIdx.x; k < cnt; k += stride) {
        unsigned p = g_work[k];
        int i = (int)(p >> 11);
        int j = (int)(p & 2047u);
        float px[4], py[4], qx[4], qy[4];
#pragma unroll
        for (int c = 0; c < 4; c++) {
            px[c] = g_px[i * 4 + c]; py[c] = g_py[i * 4 + c];
            qx[c] = g_px[j * 4 + c]; qy[c] = g_py[j * 4 + c];
        }
        float inter = pair_inter(px, py, qx, qy);
        float ai = g_area[i], aj = g_area[j];
        float uni = ai + aj - inter;
        float iou = inter / fmaxf(uni, FEPS);
        if (iou > THRESH)
            atomicOr(&g_mask[(size_t)i * CB + (j >> 6)], 1ULL << (j & 63));
    }
}

// ---------------------------------------------------------------------------
// Kernel 4: serial greedy reduce (1 warp; lane owns one 64-bit remv word).
// One-row prefetch hides the L2 latency of the mask row load.
// OUTPUT IS float32: indices as floats, padded with -1.0f.
// ---------------------------------------------------------------------------
__global__ void reduce_kernel(int n, float* __restrict__ out, int out_size) {
    const int lane = threadIdx.x;  // 32 lanes
    unsigned long long remv = 0ULL;
    unsigned long long cur = g_mask[lane];  // row 0 prefetch
    int num = 0;
    for (int i = 0; i < n; i++) {
        unsigned long long nxt = (i + 1 < n) ? g_mask[(size_t)(i + 1) * CB + lane] : 0ULL;
        int b = i >> 6;
        unsigned long long w = __shfl_sync(0xffffffffu, remv, b);
        if (!((w >> (i & 63)) & 1ULL)) {
            if (lane == 0 && num < out_size) out[num] = (float)i;
            num++;
            remv |= cur;
        }
        cur = nxt;
    }
    if (lane == 0) {
        for (int k = num; k < out_size; k++) out[k] = -1.0f;
    }
}

// ---------------------------------------------------------------------------
extern "C" void kernel_launch(void* const* d_in, const int* in_sizes, int n_in,
                              void* d_out, int out_size) {
    const float* boxes = (const float*)d_in[0];
    int n = in_sizes[0] / 5;

    corners_kernel<<<(n + 127) / 128, 128>>>(boxes, n);

    int rb = (n + TPB - 1) / TPB;  // 32 for n=2000
    dim3 grid(rb, rb);
    filter_kernel<<<grid, TPB>>>(n);

    clip_kernel<<<592, 128>>>();

    reduce_kernel<<<1, 32>>>(n, (float*)d_out, out_size);
}

// round 5
// speedup vs baseline: 2.4081x; 1.8874x over previous
#include <cuda_runtime.h>
#include <math.h>

#define NMAX   2048
#define CB     32          // column blocks of 64 -> supports up to 2048 boxes
#define TPB    64
#define FEPS   1e-8f
#define THRESH 0.7f
#define CAP    (NMAX * NMAX / 2)   // worklist capacity (worst case)
#define SMEM_WORDS 24576           // CSR staging capacity (192KB dynamic smem)

// scratch (device globals: no allocation allowed)
__device__ float g_px[NMAX * 4];
__device__ float g_py[NMAX * 4];
__device__ float g_area[NMAX];
__device__ float g_cx[NMAX];
__device__ float g_cy[NMAX];
__device__ float g_r[NMAX];
__device__ unsigned long long g_mask[NMAX * CB];
__device__ unsigned int g_rowsum[NMAX];   // bit blk set iff mask row has bits in block blk
__device__ unsigned int g_work[CAP];      // packed pairs: (i << 11) | j
__device__ int g_count;

__device__ __forceinline__ float cross2(float ax, float ay, float bx, float by) {
    return ax * by - ay * bx;
}

// ---------------------------------------------------------------------------
// Kernel 1: corners + per-box metadata (+ zero worklist counter)
// ---------------------------------------------------------------------------
__global__ void corners_kernel(const float* __restrict__ boxes, int n) {
    int i = blockIdx.x * blockDim.x + threadIdx.x;
    if (i == 0) g_count = 0;
    if (i >= n) return;
    float xc = boxes[i * 5 + 0];
    float yc = boxes[i * 5 + 1];
    float w  = boxes[i * 5 + 2];
    float h  = boxes[i * 5 + 3];
    float t  = boxes[i * 5 + 4];
    float th = t * (float)(M_PI / 180.0);
    float c = cosf(th), s = sinf(th);
    const float lx[4] = {0.5f, -0.5f, -0.5f, 0.5f};
    const float ly[4] = {0.5f, 0.5f, -0.5f, -0.5f};
#pragma unroll
    for (int k = 0; k < 4; k++) {
        g_px[i * 4 + k] = xc + lx[k] * w * c - ly[k] * h * s;
        g_py[i * 4 + k] = yc + lx[k] * w * s + ly[k] * h * c;
    }
    g_area[i] = w * h;
    g_cx[i] = xc;
    g_cy[i] = yc;
    g_r[i]  = 0.5f * sqrtf(w * w + h * h);
}

// ---------------------------------------------------------------------------
// Kernel 2: cheap exact-safe filters over all upper-triangle pairs.
// Survivors pushed (warp-aggregated) into g_work. Also zeroes g_mask/g_rowsum.
// ---------------------------------------------------------------------------
__global__ void filter_kernel(int n) {
    const int colb = blockIdx.x;
    const int rowb = blockIdx.y;
    const int row = rowb * TPB + threadIdx.x;

    // zero this row's mask word for this column block (+ summary once)
    if (row < n) {
        g_mask[(size_t)row * CB + colb] = 0ULL;
        if (colb == 0) g_rowsum[row] = 0u;
    }
    if (colb < rowb) return;   // uniform per block

    __shared__ float sarea[TPB], scx[TPB], scy[TPB], sr[TPB];
    const int col0 = colb * TPB;
    {
        int t = threadIdx.x;
        int j = col0 + t;
        if (j < n) {
            sarea[t] = g_area[j];
            scx[t] = g_cx[j];
            scy[t] = g_cy[j];
            sr[t]  = g_r[j];
        }
    }
    __syncthreads();

    const int colsz = min(TPB, n - col0);
    const bool rowvalid = (row < n);
    const int rload = rowvalid ? row : (n - 1);
    const float ai  = g_area[rload];
    const float cxi = g_cx[rload], cyi = g_cy[rload], ri = g_r[rload];
    const bool diag = (colb == rowb);
    const int lane = threadIdx.x & 31;

    for (int jj = 0; jj < colsz; jj++) {
        bool hit = rowvalid && (!diag || jj > threadIdx.x);
        if (hit) {
            float aj = sarea[jj];
            float amin = fminf(ai, aj), amax = fmaxf(ai, aj);
            float dx = cxi - scx[jj], dy = cyi - scy[jj];
            float rr = ri + sr[jj];
            hit = (amin > THRESH * amax) && (dx * dx + dy * dy < rr * rr);
        }
        unsigned b = __ballot_sync(0xffffffffu, hit);
        if (b) {
            int leader = __ffs(b) - 1;
            int base = 0;
            if (lane == leader) base = atomicAdd(&g_count, __popc(b));
            base = __shfl_sync(0xffffffffu, base, leader);
            if (hit) {
                int idx = base + __popc(b & ((1u << lane) - 1u));
                if (idx < CAP)
                    g_work[idx] = ((unsigned)row << 11) | (unsigned)(col0 + jj);
            }
        }
    }
}

// ---------------------------------------------------------------------------
// Exact replica of the reference _pair_inter_area (compacted form).
// ---------------------------------------------------------------------------
__device__ float pair_inter(const float* __restrict__ px, const float* __restrict__ py,
                            const float* __restrict__ qx, const float* __restrict__ qy) {
    float d1x[4], d1y[4], d2x[4], d2y[4];
#pragma unroll
    for (int k = 0; k < 4; k++) {
        int k1 = (k + 1) & 3;
        d1x[k] = px[k1] - px[k]; d1y[k] = py[k1] - py[k];
        d2x[k] = qx[k1] - qx[k]; d2y[k] = qy[k1] - qy[k];
    }
    float X[24], Y[24];
    int m = 0;
    // edge-edge intersections (16 candidates)
#pragma unroll
    for (int k = 0; k < 4; k++) {
#pragma unroll
        for (int l = 0; l < 4; l++) {
            float den = cross2(d1x[k], d1y[k], d2x[l], d2y[l]);
            if (fabsf(den) > FEPS) {
                float rx = qx[l] - px[k], ry = qy[l] - py[k];
                float t = cross2(rx, ry, d2x[l], d2y[l]) / den;
                float u = cross2(rx, ry, d1x[k], d1y[k]) / den;
                if (t >= 0.f && t <= 1.f && u >= 0.f && u <= 1.f) {
                    X[m] = px[k] + t * d1x[k];
                    Y[m] = py[k] + t * d1y[k];
                    m++;
                }
            }
        }
    }
    // c1 vertices inside c2
#pragma unroll
    for (int k = 0; k < 4; k++) {
        bool pos = true, neg = true;
#pragma unroll
        for (int l = 0; l < 4; l++) {
            float cr = cross2(d2x[l], d2y[l], px[k] - qx[l], py[k] - qy[l]);
            pos = pos && (cr >= -FEPS);
            neg = neg && (cr <= FEPS);
        }
        if (pos || neg) { X[m] = px[k]; Y[m] = py[k]; m++; }
    }
    // c2 vertices inside c1
#pragma unroll
    for (int k = 0; k < 4; k++) {
        bool pos = true, neg = true;
#pragma unroll
        for (int l = 0; l < 4; l++) {
            float cr = cross2(d1x[l], d1y[l], qx[k] - px[l], qy[k] - py[l]);
            pos = pos && (cr >= -FEPS);
            neg = neg && (cr <= FEPS);
        }
        if (pos || neg) { X[m] = qx[k]; Y[m] = qy[k]; m++; }
    }
    if (m < 3) return 0.f;

    float cx = 0.f, cy = 0.f;
    for (int i = 0; i < m; i++) { cx += X[i]; cy += Y[i]; }
    float inv = 1.f / (float)m;
    cx *= inv; cy *= inv;

    float ang[24];
    for (int i = 0; i < m; i++) ang[i] = atan2f(Y[i] - cy, X[i] - cx);

    // stable insertion sort by angle
    for (int i = 1; i < m; i++) {
        float a = ang[i], x = X[i], y = Y[i];
        int j = i - 1;
        while (j >= 0 && ang[j] > a) {
            ang[j + 1] = ang[j]; X[j + 1] = X[j]; Y[j + 1] = Y[j];
            j--;
        }
        ang[j + 1] = a; X[j + 1] = x; Y[j + 1] = y;
    }

    float area = 0.f;
    for (int i = 0; i < m; i++) {
        int j = (i + 1 == m) ? 0 : i + 1;
        area += cross2(X[i] - cx, Y[i] - cy, X[j] - cx, Y[j] - cy);
    }
    return 0.5f * fabsf(area);
}

// ---------------------------------------------------------------------------
// Kernel 3: exact clip, one thread per surviving pair (grid-stride).
// ---------------------------------------------------------------------------
__global__ void clip_kernel() {
    int cnt = g_count;
    if (cnt > CAP) cnt = CAP;
    const int stride = gridDim.x * blockDim.x;
    for (int k = blockIdx.x * blockDim.x + threadIdx.x; k < cnt; k += stride) {
        unsigned p = g_work[k];
        int i = (int)(p >> 11);
        int j = (int)(p & 2047u);
        float px[4], py[4], qx[4], qy[4];
#pragma unroll
        for (int c = 0; c < 4; c++) {
            px[c] = g_px[i * 4 + c]; py[c] = g_py[i * 4 + c];
            qx[c] = g_px[j * 4 + c]; qy[c] = g_py[j * 4 + c];
        }
        float inter = pair_inter(px, py, qx, qy);
        float ai = g_area[i], aj = g_area[j];
        float uni = ai + aj - inter;
        float iou = inter / fmaxf(uni, FEPS);
        if (iou > THRESH) {
            int blk = j >> 6;
            atomicOr(&g_mask[(size_t)i * CB + blk], 1ULL << (j & 63));
            atomicOr(&g_rowsum[i], 1u << blk);
        }
    }
}

// ---------------------------------------------------------------------------
// Kernel 4 (v2): serial greedy, fully latency-decoupled.
//  - 2048-bit remv bitset lives in warp registers (lane l owns block l).
//  - Preload phase builds a compact SMEM CSR of the (sparse) nonzero mask
//    words, driven by g_rowsum. Throughput-bound, not latency-bound.
//  - Main loop: 1 SHFL per 64 rows; per-row critical path is a register bit
//    test; summaries software-pipelined (LDS hidden); suppressor rows hit
//    SMEM (29 cyc) not L2 (234 cyc). All control flow is warp-uniform.
// ---------------------------------------------------------------------------
__global__ void reduce_kernel(int n, float* __restrict__ out, int out_size) {
    __shared__ unsigned s_sum[NMAX];   // row summaries
    __shared__ unsigned s_off[NMAX];   // CSR offsets into s_words
    extern __shared__ unsigned long long s_words[];  // compact nonzero mask words

    const int lane = threadIdx.x;

    // ---- preload + CSR build (warp-cooperative) ----
    unsigned base = 0;
    for (int r0 = 0; r0 < NMAX; r0 += 32) {
        int i = r0 + lane;
        unsigned s = (i < n) ? g_rowsum[i] : 0u;
        s_sum[i] = s;
        unsigned c = __popc(s);
        unsigned sc = c;
#pragma unroll
        for (int d = 1; d < 32; d <<= 1) {
            unsigned v = __shfl_up_sync(0xffffffffu, sc, d);
            if (lane >= d) sc += v;
        }
        unsigned off = base + sc - c;
        s_off[i] = off;
        base += __shfl_sync(0xffffffffu, sc, 31);
        // copy this row's nonzero words into the CSR
        unsigned ss = s;
        unsigned o = off;
        while (ss) {
            int blk = __ffs(ss) - 1;
            ss &= ss - 1;
            if (o < SMEM_WORDS)
                s_words[o] = g_mask[(size_t)i * CB + blk];
            o++;
        }
    }
    __syncwarp();

    // ---- serial greedy ----
    unsigned long long word = 0ULL;   // lane's remv block
    int num = 0;
    unsigned sv = s_sum[0];           // pipelined summary
    for (int b = 0; b < CB; b++) {
        const int i0 = b * 64;
        if (i0 >= n) break;
        unsigned long long cur = __shfl_sync(0xffffffffu, word, b);
        const int iend = min(64, n - i0);
        for (int t = 0; t < iend; t++) {
            const int i = i0 + t;
            const unsigned s_cur = sv;
            sv = s_sum[(i + 1) & (NMAX - 1)];   // prefetch next (wraps harmlessly)
            if (!((cur >> t) & 1ULL)) {
                if (lane == 0 && num < out_size) out[num] = (float)i;
                num++;
                unsigned s = s_cur;
                if (s) {
                    unsigned o = s_off[i];
                    do {
                        int blk = __ffs(s) - 1;
                        s &= s - 1;
                        unsigned long long w = (o < SMEM_WORDS)
                            ? s_words[o]
                            : g_mask[(size_t)i * CB + blk];
                        o++;
                        if (blk == b) cur |= w;          // affects this block now
                        if (lane == blk) word |= w;      // owner lane records it
                    } while (s);
                }
            }
        }
    }
    if (lane == 0) {
        for (int k = num; k < out_size; k++) out[k] = -1.0f;
    }
}

// ---------------------------------------------------------------------------
extern "C" void kernel_launch(void* const* d_in, const int* in_sizes, int n_in,
                              void* d_out, int out_size) {
    const float* boxes = (const float*)d_in[0];
    int n = in_sizes[0] / 5;

    corners_kernel<<<(n + 127) / 128, 128>>>(boxes, n);

    int rb = (n + TPB - 1) / TPB;  // 32 for n=2000
    dim3 grid(rb, rb);
    filter_kernel<<<grid, TPB>>>(n);

    clip_kernel<<<592, 128>>>();

    cudaFuncSetAttribute(reduce_kernel,
                         cudaFuncAttributeMaxDynamicSharedMemorySize,
                         SMEM_WORDS * (int)sizeof(unsigned long long));
    reduce_kernel<<<1, 32, SMEM_WORDS * sizeof(unsigned long long)>>>(
        n, (float*)d_out, out_size);
}

// round 6
// speedup vs baseline: 3.2768x; 1.3608x over previous
#include <cuda_runtime.h>
#include <math.h>

#define NMAX   2048
#define CB     32          // column blocks of 64 -> supports up to 2048 boxes
#define TPB    64
#define FEPS   1e-8f
#define THRESH 0.7f
#define CAP    (NMAX * NMAX / 2)   // worklist capacity (worst case)
#define SMEM_WORDS 24576           // CSR staging capacity (192KB dynamic smem)
#define FULLM  0xffffffffu

// scratch (device globals: no allocation allowed)
__device__ float g_px[NMAX * 4];
__device__ float g_py[NMAX * 4];
__device__ float g_area[NMAX];
__device__ float g_cx[NMAX];
__device__ float g_cy[NMAX];
__device__ float g_r[NMAX];
__device__ unsigned long long g_mask[NMAX * CB];
__device__ unsigned int g_rowsum[NMAX];   // bit blk set iff mask row has bits in block blk
__device__ unsigned int g_work[CAP];      // packed pairs: (i << 11) | j
__device__ int g_count;

__device__ __forceinline__ float cross2(float ax, float ay, float bx, float by) {
    return ax * by - ay * bx;
}

// ---------------------------------------------------------------------------
// Kernel 1: corners + per-box metadata (+ zero worklist counter)
// ---------------------------------------------------------------------------
__global__ void corners_kernel(const float* __restrict__ boxes, int n) {
    int i = blockIdx.x * blockDim.x + threadIdx.x;
    if (i == 0) g_count = 0;
    if (i >= n) return;
    float xc = boxes[i * 5 + 0];
    float yc = boxes[i * 5 + 1];
    float w  = boxes[i * 5 + 2];
    float h  = boxes[i * 5 + 3];
    float t  = boxes[i * 5 + 4];
    float th = t * (float)(M_PI / 180.0);
    float c = cosf(th), s = sinf(th);
    const float lx[4] = {0.5f, -0.5f, -0.5f, 0.5f};
    const float ly[4] = {0.5f, 0.5f, -0.5f, -0.5f};
#pragma unroll
    for (int k = 0; k < 4; k++) {
        g_px[i * 4 + k] = xc + lx[k] * w * c - ly[k] * h * s;
        g_py[i * 4 + k] = yc + lx[k] * w * s + ly[k] * h * c;
    }
    g_area[i] = w * h;
    g_cx[i] = xc;
    g_cy[i] = yc;
    g_r[i]  = 0.5f * sqrtf(w * w + h * h);
}

// ---------------------------------------------------------------------------
// Kernel 2: cheap exact-safe filters over all upper-triangle pairs.
// Survivors pushed (warp-aggregated) into g_work. Also zeroes g_mask/g_rowsum.
// ---------------------------------------------------------------------------
__global__ void filter_kernel(int n) {
    const int colb = blockIdx.x;
    const int rowb = blockIdx.y;
    const int row = rowb * TPB + threadIdx.x;

    // zero this row's mask word for this column block (+ summary once)
    if (row < n) {
        g_mask[(size_t)row * CB + colb] = 0ULL;
        if (colb == 0) g_rowsum[row] = 0u;
    }
    if (colb < rowb) return;   // uniform per block

    __shared__ float sarea[TPB], scx[TPB], scy[TPB], sr[TPB];
    const int col0 = colb * TPB;
    {
        int t = threadIdx.x;
        int j = col0 + t;
        if (j < n) {
            sarea[t] = g_area[j];
            scx[t] = g_cx[j];
            scy[t] = g_cy[j];
            sr[t]  = g_r[j];
        }
    }
    __syncthreads();

    const int colsz = min(TPB, n - col0);
    const bool rowvalid = (row < n);
    const int rload = rowvalid ? row : (n - 1);
    const float ai  = g_area[rload];
    const float cxi = g_cx[rload], cyi = g_cy[rload], ri = g_r[rload];
    const bool diag = (colb == rowb);
    const int lane = threadIdx.x & 31;

    for (int jj = 0; jj < colsz; jj++) {
        bool hit = rowvalid && (!diag || jj > threadIdx.x);
        if (hit) {
            float aj = sarea[jj];
            float amin = fminf(ai, aj), amax = fmaxf(ai, aj);
            float dx = cxi - scx[jj], dy = cyi - scy[jj];
            float rr = ri + sr[jj];
            hit = (amin > THRESH * amax) && (dx * dx + dy * dy < rr * rr);
        }
        unsigned b = __ballot_sync(FULLM, hit);
        if (b) {
            int leader = __ffs(b) - 1;
            int base = 0;
            if (lane == leader) base = atomicAdd(&g_count, __popc(b));
            base = __shfl_sync(FULLM, base, leader);
            if (hit) {
                int idx = base + __popc(b & ((1u << lane) - 1u));
                if (idx < CAP)
                    g_work[idx] = ((unsigned)row << 11) | (unsigned)(col0 + jj);
            }
        }
    }
}

// ---------------------------------------------------------------------------
// Exact replica of the reference _pair_inter_area (compacted form).
// ---------------------------------------------------------------------------
__device__ float pair_inter(const float* __restrict__ px, const float* __restrict__ py,
                            const float* __restrict__ qx, const float* __restrict__ qy) {
    float d1x[4], d1y[4], d2x[4], d2y[4];
#pragma unroll
    for (int k = 0; k < 4; k++) {
        int k1 = (k + 1) & 3;
        d1x[k] = px[k1] - px[k]; d1y[k] = py[k1] - py[k];
        d2x[k] = qx[k1] - qx[k]; d2y[k] = qy[k1] - qy[k];
    }
    float X[24], Y[24];
    int m = 0;
    // edge-edge intersections (16 candidates)
#pragma unroll
    for (int k = 0; k < 4; k++) {
#pragma unroll
        for (int l = 0; l < 4; l++) {
            float den = cross2(d1x[k], d1y[k], d2x[l], d2y[l]);
            if (fabsf(den) > FEPS) {
                float rx = qx[l] - px[k], ry = qy[l] - py[k];
                float t = cross2(rx, ry, d2x[l], d2y[l]) / den;
                float u = cross2(rx, ry, d1x[k], d1y[k]) / den;
                if (t >= 0.f && t <= 1.f && u >= 0.f && u <= 1.f) {
                    X[m] = px[k] + t * d1x[k];
                    Y[m] = py[k] + t * d1y[k];
                    m++;
                }
            }
        }
    }
    // c1 vertices inside c2
#pragma unroll
    for (int k = 0; k < 4; k++) {
        bool pos = true, neg = true;
#pragma unroll
        for (int l = 0; l < 4; l++) {
            float cr = cross2(d2x[l], d2y[l], px[k] - qx[l], py[k] - qy[l]);
            pos = pos && (cr >= -FEPS);
            neg = neg && (cr <= FEPS);
        }
        if (pos || neg) { X[m] = px[k]; Y[m] = py[k]; m++; }
    }
    // c2 vertices inside c1
#pragma unroll
    for (int k = 0; k < 4; k++) {
        bool pos = true, neg = true;
#pragma unroll
        for (int l = 0; l < 4; l++) {
            float cr = cross2(d1x[l], d1y[l], qx[k] - px[l], qy[k] - py[l]);
            pos = pos && (cr >= -FEPS);
            neg = neg && (cr <= FEPS);
        }
        if (pos || neg) { X[m] = qx[k]; Y[m] = qy[k]; m++; }
    }
    if (m < 3) return 0.f;

    float cx = 0.f, cy = 0.f;
    for (int i = 0; i < m; i++) { cx += X[i]; cy += Y[i]; }
    float inv = 1.f / (float)m;
    cx *= inv; cy *= inv;

    float ang[24];
    for (int i = 0; i < m; i++) ang[i] = atan2f(Y[i] - cy, X[i] - cx);

    // stable insertion sort by angle
    for (int i = 1; i < m; i++) {
        float a = ang[i], x = X[i], y = Y[i];
        int j = i - 1;
        while (j >= 0 && ang[j] > a) {
            ang[j + 1] = ang[j]; X[j + 1] = X[j]; Y[j + 1] = Y[j];
            j--;
        }
        ang[j + 1] = a; X[j + 1] = x; Y[j + 1] = y;
    }

    float area = 0.f;
    for (int i = 0; i < m; i++) {
        int j = (i + 1 == m) ? 0 : i + 1;
        area += cross2(X[i] - cx, Y[i] - cy, X[j] - cx, Y[j] - cy);
    }
    return 0.5f * fabsf(area);
}

// ---------------------------------------------------------------------------
// Kernel 3: exact clip, one thread per surviving pair (grid-stride).
// ---------------------------------------------------------------------------
__global__ void clip_kernel() {
    int cnt = g_count;
    if (cnt > CAP) cnt = CAP;
    const int stride = gridDim.x * blockDim.x;
    for (int k = blockIdx.x * blockDim.x + threadIdx.x; k < cnt; k += stride) {
        unsigned p = g_work[k];
        int i = (int)(p >> 11);
        int j = (int)(p & 2047u);
        float px[4], py[4], qx[4], qy[4];
#pragma unroll
        for (int c = 0; c < 4; c++) {
            px[c] = g_px[i * 4 + c]; py[c] = g_py[i * 4 + c];
            qx[c] = g_px[j * 4 + c]; qy[c] = g_py[j * 4 + c];
        }
        float inter = pair_inter(px, py, qx, qy);
        float ai = g_area[i], aj = g_area[j];
        float uni = ai + aj - inter;
        float iou = inter / fmaxf(uni, FEPS);
        if (iou > THRESH) {
            int blk = j >> 6;
            atomicOr(&g_mask[(size_t)i * CB + blk], 1ULL << (j & 63));
            atomicOr(&g_rowsum[i], 1u << blk);
        }
    }
}

// ---------------------------------------------------------------------------
// Kernel 4 (v3): event-driven serial greedy.
//  - remv bitset in registers (lane b owns block b), CSR of nonzero mask
//    words in SMEM (as v2).
//  - NEW: per-block 64-bit `act` word (suppressor rows), in registers.
//    The greedy walk visits only set bits of act&~remv (events), not every
//    row: ~300 events instead of 2000 row iterations.
//  - Output = ffsll walk over kept = valid & ~cur (final after the event
//    walk, since suppression only flows forward).
//  - Early exit once out_size indices are emitted (output only needs the
//    first out_size kept rows).
// ---------------------------------------------------------------------------
__global__ void reduce_kernel(int n, float* __restrict__ out, int out_size) {
    __shared__ unsigned s_sum[NMAX];   // row summaries
    __shared__ unsigned s_off[NMAX];   // CSR offsets into s_words
    extern __shared__ unsigned long long s_words[];  // compact nonzero mask words

    const int lane = threadIdx.x;

    // ---- preload + CSR build (warp-cooperative) ----
    unsigned base = 0;
    unsigned long long act_reg = 0ULL;  // lane b holds active-rows word of block b
    for (int r0 = 0; r0 < NMAX; r0 += 32) {
        int i = r0 + lane;
        unsigned s = (i < n) ? g_rowsum[i] : 0u;
        s_sum[i] = s;
        unsigned bm = __ballot_sync(FULLM, s != 0u);
        {
            int blk = r0 >> 6;
            int half = (r0 >> 5) & 1;
            if (lane == blk)
                act_reg |= ((unsigned long long)bm) << (32 * half);
        }
        unsigned c = __popc(s);
        unsigned sc = c;
#pragma unroll
        for (int d = 1; d < 32; d <<= 1) {
            unsigned v = __shfl_up_sync(FULLM, sc, d);
            if (lane >= d) sc += v;
        }
        unsigned off = base + sc - c;
        s_off[i] = off;
        base += __shfl_sync(FULLM, sc, 31);
        // copy this row's nonzero words into the CSR
        unsigned ss = s;
        unsigned o = off;
        while (ss) {
            int blk = __ffs(ss) - 1;
            ss &= ss - 1;
            if (o < SMEM_WORDS)
                s_words[o] = g_mask[(size_t)i * CB + blk];
            o++;
        }
    }
    __syncwarp();

    // ---- event-driven greedy ----
    unsigned long long word = 0ULL;   // lane's remv block
    int num = 0;
    for (int b = 0; b < CB; b++) {
        const int i0 = b * 64;
        if (i0 >= n || num >= out_size) break;
        unsigned long long cur = __shfl_sync(FULLM, word, b);
        unsigned long long act = __shfl_sync(FULLM, act_reg, b);
        const int nvalid = min(64, n - i0);
        const unsigned long long valid =
            (nvalid == 64) ? ~0ULL : ((1ULL << nvalid) - 1ULL);

        // suppressor-event walk (ascending row order == serial greedy order)
        unsigned long long a = act & valid & ~cur;
        while (a) {
            int t = __ffsll(a) - 1;
            a &= a - 1;                       // clear this event
            const int i = i0 + t;
            unsigned s = s_sum[i];
            unsigned o = s_off[i];
            do {
                int blk = __ffs(s) - 1;
                s &= s - 1;
                unsigned long long w = (o < SMEM_WORDS)
                    ? s_words[o]
                    : g_mask[(size_t)i * CB + blk];
                o++;
                if (blk == b) cur |= w;       // in-block suppression, live now
                if (lane == blk) word |= w;   // future blocks, owner lane
            } while (s);
            a &= ~cur;                        // drop now-suppressed events
        }

        // emit kept rows of this block (cur is final for this block)
        unsigned long long kept = valid & ~cur;
        while (kept && num < out_size) {
            int t = __ffsll(kept) - 1;
            kept &= kept - 1;
            if (lane == 0) out[num] = (float)(i0 + t);
            num++;
        }
    }
    if (lane == 0) {
        for (int k = num; k < out_size; k++) out[k] = -1.0f;
    }
}

// ---------------------------------------------------------------------------
extern "C" void kernel_launch(void* const* d_in, const int* in_sizes, int n_in,
                              void* d_out, int out_size) {
    const float* boxes = (const float*)d_in[0];
    int n = in_sizes[0] / 5;

    corners_kernel<<<(n + 127) / 128, 128>>>(boxes, n);

    int rb = (n + TPB - 1) / TPB;  // 32 for n=2000
    dim3 grid(rb, rb);
    filter_kernel<<<grid, TPB>>>(n);

    clip_kernel<<<592, 128>>>();

    cudaFuncSetAttribute(reduce_kernel,
                         cudaFuncAttributeMaxDynamicSharedMemorySize,
                         SMEM_WORDS * (int)sizeof(unsigned long long));
    reduce_kernel<<<1, 32, SMEM_WORDS * sizeof(unsigned long long)>>>(
        n, (float*)d_out, out_size);
}

// round 9
// speedup vs baseline: 9.7129x; 2.9641x over previous
#include <cuda_runtime.h>
#include <math.h>

#define NMAX   2048
#define CB     32          // 64-wide bit blocks -> supports up to 2048 boxes
#define TPB    64
#define RTPB   1024
#define FEPS   1e-8f
#define THRESH 0.7f
#define CAP    (NMAX * NMAX / 2)   // worklist capacity (worst case)
#define FULLM  0xffffffffu

// scratch (device globals: no allocation allowed)
__device__ float g_px[NMAX * 4];
__device__ float g_py[NMAX * 4];
__device__ float g_area[NMAX];
__device__ float g_cx[NMAX];
__device__ float g_cy[NMAX];
__device__ float g_r[NMAX];
__device__ unsigned long long g_maskT[NMAX * CB]; // maskT[j] bit i: box i (<j) suppresses j
__device__ unsigned int g_colsum[NMAX];           // bit blk set iff maskT row j has bits in i-block blk
__device__ unsigned int g_work[CAP];              // packed pairs: (i << 11) | j
__device__ int g_count;

__device__ __forceinline__ float cross2(float ax, float ay, float bx, float by) {
    return ax * by - ay * bx;
}

// ---------------------------------------------------------------------------
// Kernel 1: corners + per-box metadata (+ zero worklist counter)
// ---------------------------------------------------------------------------
__global__ void corners_kernel(const float* __restrict__ boxes, int n) {
    int i = blockIdx.x * blockDim.x + threadIdx.x;
    if (i == 0) g_count = 0;
    if (i >= n) return;
    float xc = boxes[i * 5 + 0];
    float yc = boxes[i * 5 + 1];
    float w  = boxes[i * 5 + 2];
    float h  = boxes[i * 5 + 3];
    float t  = boxes[i * 5 + 4];
    float th = t * (float)(M_PI / 180.0);
    float c = cosf(th), s = sinf(th);
    const float lx[4] = {0.5f, -0.5f, -0.5f, 0.5f};
    const float ly[4] = {0.5f, 0.5f, -0.5f, -0.5f};
#pragma unroll
    for (int k = 0; k < 4; k++) {
        g_px[i * 4 + k] = xc + lx[k] * w * c - ly[k] * h * s;
        g_py[i * 4 + k] = yc + lx[k] * w * s + ly[k] * h * c;
    }
    g_area[i] = w * h;
    g_cx[i] = xc;
    g_cy[i] = yc;
    g_r[i]  = 0.5f * sqrtf(w * w + h * h);
}

// ---------------------------------------------------------------------------
// Kernel 2: cheap exact-safe filters over all upper-triangle pairs.
// Survivors pushed (warp-aggregated) into g_work. Also zeroes maskT/colsum.
// ---------------------------------------------------------------------------
__global__ void filter_kernel(int n) {
    const int colb = blockIdx.x;
    const int rowb = blockIdx.y;
    const int row = rowb * TPB + threadIdx.x;

    // zero this row's transposed-mask word for this i-block (+ summary once)
    if (row < n) {
        g_maskT[(size_t)row * CB + colb] = 0ULL;
        if (colb == 0) g_colsum[row] = 0u;
    }
    if (colb < rowb) return;   // uniform per block

    __shared__ float sarea[TPB], scx[TPB], scy[TPB], sr[TPB];
    const int col0 = colb * TPB;
    {
        int t = threadIdx.x;
        int j = col0 + t;
        if (j < n) {
            sarea[t] = g_area[j];
            scx[t] = g_cx[j];
            scy[t] = g_cy[j];
            sr[t]  = g_r[j];
        }
    }
    __syncthreads();

    const int colsz = min(TPB, n - col0);
    const bool rowvalid = (row < n);
    const int rload = rowvalid ? row : (n - 1);
    const float ai  = g_area[rload];
    const float cxi = g_cx[rload], cyi = g_cy[rload], ri = g_r[rload];
    const bool diag = (colb == rowb);
    const int lane = threadIdx.x & 31;

    for (int jj = 0; jj < colsz; jj++) {
        bool hit = rowvalid && (!diag || jj > threadIdx.x);
        if (hit) {
            float aj = sarea[jj];
            float amin = fminf(ai, aj), amax = fmaxf(ai, aj);
            float dx = cxi - scx[jj], dy = cyi - scy[jj];
            float rr = ri + sr[jj];
            hit = (amin > THRESH * amax) && (dx * dx + dy * dy < rr * rr);
        }
        unsigned b = __ballot_sync(FULLM, hit);
        if (b) {
            int leader = __ffs(b) - 1;
            int base = 0;
            if (lane == leader) base = atomicAdd(&g_count, __popc(b));
            base = __shfl_sync(FULLM, base, leader);
            if (hit) {
                int idx = base + __popc(b & ((1u << lane) - 1u));
                if (idx < CAP)
                    g_work[idx] = ((unsigned)row << 11) | (unsigned)(col0 + jj);
            }
        }
    }
}

// ---------------------------------------------------------------------------
// Exact replica of the reference _pair_inter_area (compacted form).
// ---------------------------------------------------------------------------
__device__ float pair_inter(const float* __restrict__ px, const float* __restrict__ py,
                            const float* __restrict__ qx, const float* __restrict__ qy) {
    float d1x[4], d1y[4], d2x[4], d2y[4];
#pragma unroll
    for (int k = 0; k < 4; k++) {
        int k1 = (k + 1) & 3;
        d1x[k] = px[k1] - px[k]; d1y[k] = py[k1] - py[k];
        d2x[k] = qx[k1] - qx[k]; d2y[k] = qy[k1] - qy[k];
    }
    float X[24], Y[24];
    int m = 0;
    // edge-edge intersections (16 candidates)
#pragma unroll
    for (int k = 0; k < 4; k++) {
#pragma unroll
        for (int l = 0; l < 4; l++) {
            float den = cross2(d1x[k], d1y[k], d2x[l], d2y[l]);
            if (fabsf(den) > FEPS) {
                float rx = qx[l] - px[k], ry = qy[l] - py[k];
                float t = cross2(rx, ry, d2x[l], d2y[l]) / den;
                float u = cross2(rx, ry, d1x[k], d1y[k]) / den;
                if (t >= 0.f && t <= 1.f && u >= 0.f && u <= 1.f) {
                    X[m] = px[k] + t * d1x[k];
                    Y[m] = py[k] + t * d1y[k];
                    m++;
                }
            }
        }
    }
    // c1 vertices inside c2
#pragma unroll
    for (int k = 0; k < 4; k++) {
        bool pos = true, neg = true;
#pragma unroll
        for (int l = 0; l < 4; l++) {
            float cr = cross2(d2x[l], d2y[l], px[k] - qx[l], py[k] - qy[l]);
            pos = pos && (cr >= -FEPS);
            neg = neg && (cr <= FEPS);
        }
        if (pos || neg) { X[m] = px[k]; Y[m] = py[k]; m++; }
    }
    // c2 vertices inside c1
#pragma unroll
    for (int k = 0; k < 4; k++) {
        bool pos = true, neg = true;
#pragma unroll
        for (int l = 0; l < 4; l++) {
            float cr = cross2(d1x[l], d1y[l], qx[k] - px[l], qy[k] - py[l]);
            pos = pos && (cr >= -FEPS);
            neg = neg && (cr <= FEPS);
        }
        if (pos || neg) { X[m] = qx[k]; Y[m] = qy[k]; m++; }
    }
    if (m < 3) return 0.f;

    float cx = 0.f, cy = 0.f;
    for (int i = 0; i < m; i++) { cx += X[i]; cy += Y[i]; }
    float inv = 1.f / (float)m;
    cx *= inv; cy *= inv;

    float ang[24];
    for (int i = 0; i < m; i++) ang[i] = atan2f(Y[i] - cy, X[i] - cx);

    // stable insertion sort by angle
    for (int i = 1; i < m; i++) {
        float a = ang[i], x = X[i], y = Y[i];
        int j = i - 1;
        while (j >= 0 && ang[j] > a) {
            ang[j + 1] = ang[j]; X[j + 1] = X[j]; Y[j + 1] = Y[j];
            j--;
        }
        ang[j + 1] = a; X[j + 1] = x; Y[j + 1] = y;
    }

    float area = 0.f;
    for (int i = 0; i < m; i++) {
        int j = (i + 1 == m) ? 0 : i + 1;
        area += cross2(X[i] - cx, Y[i] - cy, X[j] - cx, Y[j] - cy);
    }
    return 0.5f * fabsf(area);
}

// ---------------------------------------------------------------------------
// Kernel 3: exact clip, one thread per surviving pair (grid-stride).
// Writes the TRANSPOSED suppression matrix: maskT[j] bit i (i<j).
// ---------------------------------------------------------------------------
__global__ void clip_kernel() {
    int cnt = g_count;
    if (cnt > CAP) cnt = CAP;
    const int stride = gridDim.x * blockDim.x;
    for (int k = blockIdx.x * blockDim.x + threadIdx.x; k < cnt; k += stride) {
        unsigned p = g_work[k];
        int i = (int)(p >> 11);
        int j = (int)(p & 2047u);
        float px[4], py[4], qx[4], qy[4];
#pragma unroll
        for (int c = 0; c < 4; c++) {
            px[c] = g_px[i * 4 + c]; py[c] = g_py[i * 4 + c];
            qx[c] = g_px[j * 4 + c]; qy[c] = g_py[j * 4 + c];
        }
        float inter = pair_inter(px, py, qx, qy);
        float ai = g_area[i], aj = g_area[j];
        float uni = ai + aj - inter;
        float iou = inter / fmaxf(uni, FEPS);
        if (iou > THRESH) {
            int blk = i >> 6;
            atomicOr(&g_maskT[(size_t)j * CB + blk], 1ULL << (i & 63));
            atomicOr(&g_colsum[j], 1u << blk);
        }
    }
}

// ---------------------------------------------------------------------------
// Kernel 4 (v4): parallel Jacobi fixpoint of the greedy recurrence.
//   keep[j] = (j<n) && !exists i<j: keep[i] && M[i][j]
// Start from all-kept; iterate to no-change => unique fixpoint == serial
// greedy result (induction on suppression-DAG depth; converges in <= n
// sweeps, and we additionally cap at n sweeps for replay safety).
// 1024 threads, 2 rows each; kept bitset (64 u32 words) in SMEM; only rows
// with colsum!=0 do global loads.
// ---------------------------------------------------------------------------
__global__ void reduce_kernel(int n, float* __restrict__ out, int out_size) {
    __shared__ unsigned s_kept[64];
    __shared__ unsigned s_pref[64];
    __shared__ int s_changed;
    __shared__ int s_total;
    const int tid = threadIdx.x;
    const int j0 = tid, j1 = tid + RTPB;

    // init kept = all valid rows
    if (tid < 64) {
        int base = tid * 32;
        unsigned w = 0u;
        if (base + 32 <= n) w = FULLM;
        else if (base < n) w = (1u << (n - base)) - 1u;
        s_kept[tid] = w;
    }
    __syncthreads();

    const unsigned cs0 = (j0 < n) ? g_colsum[j0] : 0u;
    const unsigned cs1 = (j1 < n) ? g_colsum[j1] : 0u;

    for (int iter = 0; iter < n; iter++) {
        // phase A: compute new kept bits (reads s_kept only)
        bool k0, k1;
        {
            bool sup = false;
            unsigned s = cs0;
            while (s) {
                int blk = __ffs(s) - 1; s &= s - 1;
                unsigned long long m = g_maskT[(size_t)j0 * CB + blk];
                unsigned long long kw = ((unsigned long long)s_kept[blk * 2 + 1] << 32)
                                        | (unsigned long long)s_kept[blk * 2];
                if (m & kw) { sup = true; break; }
            }
            k0 = (j0 < n) && !sup;
        }
        {
            bool sup = false;
            unsigned s = cs1;
            while (s) {
                int blk = __ffs(s) - 1; s &= s - 1;
                unsigned long long m = g_maskT[(size_t)j1 * CB + blk];
                unsigned long long kw = ((unsigned long long)s_kept[blk * 2 + 1] << 32)
                                        | (unsigned long long)s_kept[blk * 2];
                if (m & kw) { sup = true; break; }
            }
            k1 = (j1 < n) && !sup;
        }
        __syncthreads();
        if (tid == 0) s_changed = 0;
        __syncthreads();
        // phase B: write ballots, detect change
        unsigned b0 = __ballot_sync(FULLM, k0);
        unsigned b1 = __ballot_sync(FULLM, k1);
        int w = tid >> 5;
        if ((tid & 31) == 0) {
            if (s_kept[w] != b0)      { s_kept[w] = b0;      s_changed = 1; }
            if (s_kept[32 + w] != b1) { s_kept[32 + w] = b1; s_changed = 1; }
        }
        __syncthreads();
        if (!s_changed) break;
    }

    // ---- emit: prefix over 64 kept words, then parallel scatter ----
    if (tid == 0) {
        int acc = 0;
        for (int w = 0; w < 64; w++) { s_pref[w] = acc; acc += __popc(s_kept[w]); }
        s_total = acc;
    }
    __syncthreads();
    const int total = s_total;

#pragma unroll
    for (int rr = 0; rr < 2; rr++) {
        int j = tid + rr * RTPB;
        if (j < n) {
            unsigned w = s_kept[j >> 5];
            if ((w >> (j & 31)) & 1u) {
                int rank = (int)s_pref[j >> 5] + __popc(w & ((1u << (j & 31)) - 1u));
                if (rank < out_size) out[rank] = (float)j;
            }
        }
    }
    for (int k = total + tid; k < out_size; k += RTPB) out[k] = -1.0f;
}

// ---------------------------------------------------------------------------
extern "C" void kernel_launch(void* const* d_in, const int* in_sizes, int n_in,
                              void* d_out, int out_size) {
    const float* boxes = (const float*)d_in[0];
    int n = in_sizes[0] / 5;

    corners_kernel<<<(n + 127) / 128, 128>>>(boxes, n);

    int rb = (n + TPB - 1) / TPB;  // 32 for n=2000
    dim3 grid(rb, rb);
    filter_kernel<<<grid, TPB>>>(n);

    clip_kernel<<<592, 128>>>();

    reduce_kernel<<<1, RTPB>>>(n, (float*)d_out, out_size);
}

// round 10
// speedup vs baseline: 20.1748x; 2.0771x over previous
#include <cuda_runtime.h>
#include <math.h>

#define NMAX   2048
#define CB     32          // 64-wide bit blocks -> supports up to 2048 boxes
#define TPB    64
#define RTPB   1024
#define FEPS   1e-8f
#define THRESH 0.7f
#define CAP    (NMAX * NMAX / 2)   // worklist capacity (worst case)
#define FULLM  0xffffffffu

// scratch (device globals: no allocation allowed)
__device__ unsigned long long g_maskT[NMAX * CB]; // maskT[j] bit i: box i (<j) suppresses j
__device__ unsigned int g_colsum[NMAX];           // bit blk set iff maskT row j has bits in i-block blk
__device__ unsigned int g_work[CAP];              // packed pairs: (i << 11) | j
__device__ int g_count;                           // zero-init at load; reset by reduce_kernel each run

__device__ __forceinline__ float cross2(float ax, float ay, float bx, float by) {
    return ax * by - ay * bx;
}

// ---------------------------------------------------------------------------
// Kernel 1 (filter v2): cheap exact-safe rejects over all upper-tri pairs.
//  - per-box metadata (area,cx,cy,r) computed inline from raw boxes (no trig)
//  - inner loop accumulates hits into a 64-bit word (no ballot/atomic per col)
//  - one warp scan + one atomicAdd per warp pushes survivors to g_work
//  - also zeroes g_maskT / g_colsum
// ---------------------------------------------------------------------------
__global__ void filter_kernel(const float* __restrict__ boxes, int n) {
    const int colb = blockIdx.x;
    const int rowb = blockIdx.y;
    const int row  = rowb * TPB + threadIdx.x;

    if (row < n) {
        g_maskT[(size_t)row * CB + colb] = 0ULL;
        if (colb == 0) g_colsum[row] = 0u;
    }
    if (colb < rowb) return;   // uniform per block

    __shared__ float sarea[TPB], scx[TPB], scy[TPB], sr[TPB];
    const int col0 = colb * TPB;
    {
        int t = threadIdx.x;
        int j = col0 + t;
        if (j < n) {
            float w = boxes[j * 5 + 2], h = boxes[j * 5 + 3];
            sarea[t] = w * h;
            scx[t] = boxes[j * 5 + 0];
            scy[t] = boxes[j * 5 + 1];
            sr[t]  = 0.5f * sqrtf(w * w + h * h);
        }
    }
    __syncthreads();

    const int colsz = min(TPB, n - col0);
    const bool rowvalid = (row < n);
    const int rload = rowvalid ? row : (n - 1);
    const float wR = boxes[rload * 5 + 2], hR = boxes[rload * 5 + 3];
    const float ai  = wR * hR;
    const float cxi = boxes[rload * 5 + 0], cyi = boxes[rload * 5 + 1];
    const float ri  = 0.5f * sqrtf(wR * wR + hR * hR);
    const int lane = threadIdx.x & 31;

    unsigned long long hits = 0ULL;
    for (int jj = 0; jj < colsz; jj++) {
        float aj = sarea[jj];
        float amin = fminf(ai, aj), amax = fmaxf(ai, aj);
        float dx = cxi - scx[jj], dy = cyi - scy[jj];
        float rr = ri + sr[jj];
        bool hit = (amin > THRESH * amax) && (dx * dx + dy * dy < rr * rr);
        if (hit) hits |= (1ULL << jj);
    }
    if (!rowvalid) hits = 0ULL;
    if (colb == rowb) {
        // keep only strictly-upper (jj > threadIdx.x)
        int t = threadIdx.x;
        hits &= (t >= 63) ? 0ULL : ~((2ULL << t) - 1ULL);
    }

    // warp-aggregated push: inclusive scan of counts, one atomic per warp
    unsigned c = (unsigned)__popcll(hits);
    unsigned sc = c;
#pragma unroll
    for (int d = 1; d < 32; d <<= 1) {
        unsigned v = __shfl_up_sync(FULLM, sc, d);
        if (lane >= d) sc += v;
    }
    unsigned total = __shfl_sync(FULLM, sc, 31);
    int base = 0;
    if (lane == 31 && total) base = atomicAdd(&g_count, (int)total);
    base = __shfl_sync(FULLM, base, 31);
    int off = base + (int)(sc - c);
    while (hits) {
        int jj = __ffsll(hits) - 1;
        hits &= hits - 1;
        if (off < CAP)
            g_work[off] = ((unsigned)row << 11) | (unsigned)(col0 + jj);
        off++;
    }
}

// ---------------------------------------------------------------------------
// Sutherland-Hodgman: area of intersection of two convex CCW quads.
// Clip subject (p) by the 4 half-planes of clipper (q); output vertices are
// produced in order -> shoelace directly, no centroid / atan2 / sort.
// ---------------------------------------------------------------------------
__device__ float sh_inter(const float* __restrict__ px, const float* __restrict__ py,
                          const float* __restrict__ qx, const float* __restrict__ qy) {
    float ax[12], ay[12], bx[12], by[12];
#pragma unroll
    for (int k = 0; k < 4; k++) { ax[k] = px[k]; ay[k] = py[k]; }
    int m = 4;
    float *cxv = ax, *cyv = ay, *nxv = bx, *nyv = by;
#pragma unroll
    for (int l = 0; l < 4; l++) {
        int l1 = (l + 1) & 3;
        float ex = qx[l1] - qx[l], ey = qy[l1] - qy[l];
        float ox = qx[l],         oy = qy[l];
        int nm = 0;
        float pxv = cxv[m - 1], pyv = cyv[m - 1];
        float ps = ex * (pyv - oy) - ey * (pxv - ox);
        for (int v = 0; v < m; v++) {
            float cx = cxv[v], cy = cyv[v];
            float cs = ex * (cy - oy) - ey * (cx - ox);
            if (cs >= 0.f) {
                if (ps < 0.f) {
                    float t = ps / (ps - cs);
                    nxv[nm] = pxv + t * (cx - pxv);
                    nyv[nm] = pyv + t * (cy - pyv);
                    nm++;
                }
                nxv[nm] = cx; nyv[nm] = cy; nm++;
            } else if (ps >= 0.f) {
                float t = ps / (ps - cs);
                nxv[nm] = pxv + t * (cx - pxv);
                nyv[nm] = pyv + t * (cy - pyv);
                nm++;
            }
            pxv = cx; pyv = cy; ps = cs;
        }
        m = nm;
        if (m == 0) return 0.f;
        // swap buffers
        float* t1 = cxv; cxv = nxv; nxv = t1;
        float* t2 = cyv; cyv = nyv; nyv = t2;
    }
    if (m < 3) return 0.f;
    float area = 0.f;
    int prev = m - 1;
    for (int v = 0; v < m; v++) {
        area += cxv[prev] * cyv[v] - cxv[v] * cyv[prev];
        prev = v;
    }
    return 0.5f * fabsf(area);
}

__device__ __forceinline__ void make_corners(const float* __restrict__ b, int i,
                                             float* px, float* py) {
    float xc = b[i * 5 + 0], yc = b[i * 5 + 1];
    float w  = b[i * 5 + 2], h  = b[i * 5 + 3];
    float th = b[i * 5 + 4] * (float)(M_PI / 180.0);
    float c = cosf(th), s = sinf(th);
    const float lx[4] = {0.5f, -0.5f, -0.5f, 0.5f};
    const float ly[4] = {0.5f, 0.5f, -0.5f, -0.5f};
#pragma unroll
    for (int k = 0; k < 4; k++) {
        px[k] = xc + lx[k] * w * c - ly[k] * h * s;
        py[k] = yc + lx[k] * w * s + ly[k] * h * c;
    }
}

// ---------------------------------------------------------------------------
// Kernel 2: exact clip, one thread per surviving pair (grid-stride).
// Corners recomputed inline (2 boxes / pair). Writes transposed suppression
// matrix: maskT[j] bit i (i<j). atomicOr -> deterministic.
// ---------------------------------------------------------------------------
__global__ void clip_kernel(const float* __restrict__ boxes) {
    int cnt = g_count;
    if (cnt > CAP) cnt = CAP;
    const int stride = gridDim.x * blockDim.x;
    for (int k = blockIdx.x * blockDim.x + threadIdx.x; k < cnt; k += stride) {
        unsigned p = g_work[k];
        int i = (int)(p >> 11);
        int j = (int)(p & 2047u);
        float px[4], py[4], qx[4], qy[4];
        make_corners(boxes, i, px, py);
        make_corners(boxes, j, qx, qy);
        float inter = sh_inter(px, py, qx, qy);
        float ai = boxes[i * 5 + 2] * boxes[i * 5 + 3];
        float aj = boxes[j * 5 + 2] * boxes[j * 5 + 3];
        float uni = ai + aj - inter;
        float iou = inter / fmaxf(uni, FEPS);
        if (iou > THRESH) {
            int blk = i >> 6;
            atomicOr(&g_maskT[(size_t)j * CB + blk], 1ULL << (i & 63));
            atomicOr(&g_colsum[j], 1u << blk);
        }
    }
}

// ---------------------------------------------------------------------------
// Kernel 3: parallel Jacobi fixpoint of the greedy recurrence.
//   keep[j] = (j<n) && !exists i<j: keep[i] && M[i][j]
// Unique fixpoint == serial greedy result; converges in <= DAG depth sweeps
// (hard cap n for replay safety). Also resets g_count for the next replay.
// ---------------------------------------------------------------------------
__global__ void reduce_kernel(int n, float* __restrict__ out, int out_size) {
    __shared__ unsigned s_kept[64];
    __shared__ unsigned s_pref[64];
    __shared__ int s_changed;
    __shared__ int s_total;
    const int tid = threadIdx.x;
    const int j0 = tid, j1 = tid + RTPB;

    if (tid == 0) g_count = 0;   // ready for next launch/replay (clip already read it)

    // init kept = all valid rows
    if (tid < 64) {
        int base = tid * 32;
        unsigned w = 0u;
        if (base + 32 <= n) w = FULLM;
        else if (base < n) w = (1u << (n - base)) - 1u;
        s_kept[tid] = w;
    }
    __syncthreads();

    const unsigned cs0 = (j0 < n) ? g_colsum[j0] : 0u;
    const unsigned cs1 = (j1 < n) ? g_colsum[j1] : 0u;

    for (int iter = 0; iter < n; iter++) {
        bool k0, k1;
        {
            bool sup = false;
            unsigned s = cs0;
            while (s) {
                int blk = __ffs(s) - 1; s &= s - 1;
                unsigned long long m = g_maskT[(size_t)j0 * CB + blk];
                unsigned long long kw = ((unsigned long long)s_kept[blk * 2 + 1] << 32)
                                        | (unsigned long long)s_kept[blk * 2];
                if (m & kw) { sup = true; break; }
            }
            k0 = (j0 < n) && !sup;
        }
        {
            bool sup = false;
            unsigned s = cs1;
            while (s) {
                int blk = __ffs(s) - 1; s &= s - 1;
                unsigned long long m = g_maskT[(size_t)j1 * CB + blk];
                unsigned long long kw = ((unsigned long long)s_kept[blk * 2 + 1] << 32)
                                        | (unsigned long long)s_kept[blk * 2];
                if (m & kw) { sup = true; break; }
            }
            k1 = (j1 < n) && !sup;
        }
        __syncthreads();
        if (tid == 0) s_changed = 0;
        __syncthreads();
        unsigned b0 = __ballot_sync(FULLM, k0);
        unsigned b1 = __ballot_sync(FULLM, k1);
        int w = tid >> 5;
        if ((tid & 31) == 0) {
            if (s_kept[w] != b0)      { s_kept[w] = b0;      s_changed = 1; }
            if (s_kept[32 + w] != b1) { s_kept[32 + w] = b1; s_changed = 1; }
        }
        __syncthreads();
        if (!s_changed) break;
    }

    // ---- emit: prefix over 64 kept words, then parallel scatter ----
    if (tid == 0) {
        int acc = 0;
        for (int w = 0; w < 64; w++) { s_pref[w] = acc; acc += __popc(s_kept[w]); }
        s_total = acc;
    }
    __syncthreads();
    const int total = s_total;

#pragma unroll
    for (int rr = 0; rr < 2; rr++) {
        int j = tid + rr * RTPB;
        if (j < n) {
            unsigned w = s_kept[j >> 5];
            if ((w >> (j & 31)) & 1u) {
                int rank = (int)s_pref[j >> 5] + __popc(w & ((1u << (j & 31)) - 1u));
                if (rank < out_size) out[rank] = (float)j;
            }
        }
    }
    for (int k = total + tid; k < out_size; k += RTPB) out[k] = -1.0f;
}

// ---------------------------------------------------------------------------
extern "C" void kernel_launch(void* const* d_in, const int* in_sizes, int n_in,
                              void* d_out, int out_size) {
    const float* boxes = (const float*)d_in[0];
    int n = in_sizes[0] / 5;

    int rb = (n + TPB - 1) / TPB;  // 32 for n=2000
    dim3 grid(rb, rb);
    filter_kernel<<<grid, TPB>>>(boxes, n);

    clip_kernel<<<592, 128>>>(boxes);

    reduce_kernel<<<1, RTPB>>>(n, (float*)d_out, out_size);
}

// round 11
// speedup vs baseline: 21.9832x; 1.0896x over previous
#include <cuda_runtime.h>
#include <math.h>

#define NMAX   2048
#define CB     32          // 64-wide bit blocks -> supports up to 2048 boxes
#define TPB    64
#define RTPB   1024
#define FEPS   1e-8f
#define THRESH 0.7f
#define CAP    (NMAX * NMAX / 2)   // worklist capacity (worst case)
#define FULLM  0xffffffffu

// scratch (device globals: no allocation allowed; zero-init at load,
// restored to zero by reduce_kernel's epilogue each run => replay-safe)
__device__ unsigned long long g_maskT[NMAX * CB]; // maskT[j] bit i: box i (<j) suppresses j
__device__ unsigned int g_colsum[NMAX];           // bit blk set iff maskT row j has bits in i-block blk
__device__ unsigned int g_work[CAP];              // packed pairs: (i << 11) | j
__device__ float4 g_cnr[NMAX * 2];                // corners: (x0,y0,x1,y1),(x2,y2,x3,y3)
__device__ int g_count;

// ---------------------------------------------------------------------------
// Kernel 1 (filter v3): cheap exact-safe rejects over all upper-tri pairs.
//  - column metadata packed in ONE float4 (cx,cy,area,r) -> 1 LDS.128/iter
//  - no zeroing here (reduce's epilogue restores state)
//  - diagonal blocks additionally compute+store each row's corners (once)
//  - survivors pushed via warp scan + one atomic per warp
// ---------------------------------------------------------------------------
__global__ void filter_kernel(const float* __restrict__ boxes, int n) {
    const int colb = blockIdx.x;
    const int rowb = blockIdx.y;
    if (colb < rowb) return;   // uniform per block

    __shared__ float4 smeta[TPB];   // (cx, cy, area, r)
    const int col0 = colb * TPB;
    const int t = threadIdx.x;
    const int row = rowb * TPB + t;
    {
        int j = col0 + t;
        if (j < n) {
            float w = boxes[j * 5 + 2], h = boxes[j * 5 + 3];
            smeta[t] = make_float4(boxes[j * 5 + 0], boxes[j * 5 + 1],
                                   w * h, 0.5f * sqrtf(w * w + h * h));
        } else {
            smeta[t] = make_float4(3e30f, 3e30f, 0.f, 0.f);  // sentinel: never hits
        }
    }
    // diagonal blocks compute corners for their rows (each row exactly once)
    if (colb == rowb && row < n) {
        float xc = boxes[row * 5 + 0], yc = boxes[row * 5 + 1];
        float w  = boxes[row * 5 + 2], h  = boxes[row * 5 + 3];
        float th = boxes[row * 5 + 4] * (float)(M_PI / 180.0);
        float c = cosf(th), s = sinf(th);
        const float lx[4] = {0.5f, -0.5f, -0.5f, 0.5f};
        const float ly[4] = {0.5f, 0.5f, -0.5f, -0.5f};
        float px[4], py[4];
#pragma unroll
        for (int k = 0; k < 4; k++) {
            px[k] = xc + lx[k] * w * c - ly[k] * h * s;
            py[k] = yc + lx[k] * w * s + ly[k] * h * c;
        }
        g_cnr[row * 2 + 0] = make_float4(px[0], py[0], px[1], py[1]);
        g_cnr[row * 2 + 1] = make_float4(px[2], py[2], px[3], py[3]);
    }
    __syncthreads();

    const bool rowvalid = (row < n);
    const int rload = rowvalid ? row : (n - 1);
    const float wR = boxes[rload * 5 + 2], hR = boxes[rload * 5 + 3];
    const float ai  = wR * hR;
    const float cxi = boxes[rload * 5 + 0], cyi = boxes[rload * 5 + 1];
    const float ri  = 0.5f * sqrtf(wR * wR + hR * hR);
    const int lane = t & 31;

    unsigned long long hits = 0ULL;
#pragma unroll 4
    for (int jj = 0; jj < TPB; jj++) {
        float4 mj = smeta[jj];
        float amin = fminf(ai, mj.z), amax = fmaxf(ai, mj.z);
        float dx = cxi - mj.x, dy = cyi - mj.y;
        float rr = ri + mj.w;
        bool hit = (amin > THRESH * amax) && (dx * dx + dy * dy < rr * rr);
        hits |= ((unsigned long long)hit) << jj;
    }
    if (!rowvalid) hits = 0ULL;
    if (colb == rowb)
        hits &= (t >= 63) ? 0ULL : ~((2ULL << t) - 1ULL);   // strictly upper

    // warp-aggregated push
    unsigned c = (unsigned)__popcll(hits);
    unsigned sc = c;
#pragma unroll
    for (int d = 1; d < 32; d <<= 1) {
        unsigned v = __shfl_up_sync(FULLM, sc, d);
        if (lane >= d) sc += v;
    }
    unsigned total = __shfl_sync(FULLM, sc, 31);
    int base = 0;
    if (lane == 31 && total) base = atomicAdd(&g_count, (int)total);
    base = __shfl_sync(FULLM, base, 31);
    int off = base + (int)(sc - c);
    while (hits) {
        int jj = __ffsll(hits) - 1;
        hits &= hits - 1;
        if (off < CAP)
            g_work[off] = ((unsigned)row << 11) | (unsigned)(col0 + jj);
        off++;
    }
}

// ---------------------------------------------------------------------------
// Sutherland-Hodgman: area of intersection of two convex CCW quads.
// ---------------------------------------------------------------------------
__device__ float sh_inter(const float* __restrict__ px, const float* __restrict__ py,
                          const float* __restrict__ qx, const float* __restrict__ qy) {
    float ax[12], ay[12], bx[12], by[12];
#pragma unroll
    for (int k = 0; k < 4; k++) { ax[k] = px[k]; ay[k] = py[k]; }
    int m = 4;
    float *cxv = ax, *cyv = ay, *nxv = bx, *nyv = by;
#pragma unroll
    for (int l = 0; l < 4; l++) {
        int l1 = (l + 1) & 3;
        float ex = qx[l1] - qx[l], ey = qy[l1] - qy[l];
        float ox = qx[l],         oy = qy[l];
        int nm = 0;
        float pxv = cxv[m - 1], pyv = cyv[m - 1];
        float ps = ex * (pyv - oy) - ey * (pxv - ox);
        for (int v = 0; v < m; v++) {
            float cx = cxv[v], cy = cyv[v];
            float cs = ex * (cy - oy) - ey * (cx - ox);
            if (cs >= 0.f) {
                if (ps < 0.f) {
                    float t = ps / (ps - cs);
                    nxv[nm] = pxv + t * (cx - pxv);
                    nyv[nm] = pyv + t * (cy - pyv);
                    nm++;
                }
                nxv[nm] = cx; nyv[nm] = cy; nm++;
            } else if (ps >= 0.f) {
                float t = ps / (ps - cs);
                nxv[nm] = pxv + t * (cx - pxv);
                nyv[nm] = pyv + t * (cy - pyv);
                nm++;
            }
            pxv = cx; pyv = cy; ps = cs;
        }
        m = nm;
        if (m == 0) return 0.f;
        float* t1 = cxv; cxv = nxv; nxv = t1;
        float* t2 = cyv; cyv = nyv; nyv = t2;
    }
    if (m < 3) return 0.f;
    float area = 0.f;
    int prev = m - 1;
    for (int v = 0; v < m; v++) {
        area += cxv[prev] * cyv[v] - cxv[v] * cyv[prev];
        prev = v;
    }
    return 0.5f * fabsf(area);
}

// ---------------------------------------------------------------------------
// Kernel 2: exact clip, one thread per surviving pair (grid-stride).
// Corners loaded as float4 pairs (precomputed by filter's diag blocks).
// ---------------------------------------------------------------------------
__global__ void clip_kernel(const float* __restrict__ boxes) {
    int cnt = g_count;
    if (cnt > CAP) cnt = CAP;
    const int stride = gridDim.x * blockDim.x;
    for (int k = blockIdx.x * blockDim.x + threadIdx.x; k < cnt; k += stride) {
        unsigned p = g_work[k];
        int i = (int)(p >> 11);
        int j = (int)(p & 2047u);
        float4 a0 = g_cnr[i * 2 + 0], a1 = g_cnr[i * 2 + 1];
        float4 b0 = g_cnr[j * 2 + 0], b1 = g_cnr[j * 2 + 1];
        float px[4] = {a0.x, a0.z, a1.x, a1.z};
        float py[4] = {a0.y, a0.w, a1.y, a1.w};
        float qx[4] = {b0.x, b0.z, b1.x, b1.z};
        float qy[4] = {b0.y, b0.w, b1.y, b1.w};
        float inter = sh_inter(px, py, qx, qy);
        float ai = boxes[i * 5 + 2] * boxes[i * 5 + 3];
        float aj = boxes[j * 5 + 2] * boxes[j * 5 + 3];
        float uni = ai + aj - inter;
        float iou = inter / fmaxf(uni, FEPS);
        if (iou > THRESH) {
            int blk = i >> 6;
            atomicOr(&g_maskT[(size_t)j * CB + blk], 1ULL << (i & 63));
            atomicOr(&g_colsum[j], 1u << blk);
        }
    }
}

// ---------------------------------------------------------------------------
// Kernel 3: parallel Jacobi fixpoint of the greedy recurrence.
//   keep[j] = (j<n) && !exists i<j: keep[i] && M[i][j]
// Register-cached maskT words (first 2 per row; global fallback), 2 barriers
// per sweep via double-buffered change flag. Epilogue restores all scratch
// state to zero for the next graph replay.
// ---------------------------------------------------------------------------
__global__ void reduce_kernel(int n, float* __restrict__ out, int out_size) {
    __shared__ unsigned s_kept[64];
    __shared__ unsigned s_pref[64];
    __shared__ int s_changed[2];
    __shared__ int s_total;
    const int tid = threadIdx.x;
    const int j0 = tid, j1 = tid + RTPB;

    if (tid == 0) { g_count = 0; s_changed[0] = 0; s_changed[1] = 0; }

    if (tid < 64) {
        int base = tid * 32;
        unsigned w = 0u;
        if (base + 32 <= n) w = FULLM;
        else if (base < n) w = (1u << (n - base)) - 1u;
        s_kept[tid] = w;
    }

    const unsigned cs0 = (j0 < n) ? g_colsum[j0] : 0u;
    const unsigned cs1 = (j1 < n) ? g_colsum[j1] : 0u;

    // register-cache first two maskT words per row
    unsigned long long A0 = 0, A1 = 0, B0 = 0, B1 = 0;
    int ab0 = -1, ab1 = -1, bb0 = -1, bb1 = -1;
    unsigned rest0 = 0, rest1 = 0;
    {
        unsigned s = cs0;
        if (s) { ab0 = __ffs(s) - 1; A0 = g_maskT[(size_t)j0 * CB + ab0]; s &= s - 1;
            if (s) { ab1 = __ffs(s) - 1; A1 = g_maskT[(size_t)j0 * CB + ab1]; s &= s - 1; }
            rest0 = s;
        }
        s = cs1;
        if (s) { bb0 = __ffs(s) - 1; B0 = g_maskT[(size_t)j1 * CB + bb0]; s &= s - 1;
            if (s) { bb1 = __ffs(s) - 1; B1 = g_maskT[(size_t)j1 * CB + bb1]; s &= s - 1; }
            rest1 = s;
        }
    }
    __syncthreads();

    int cur = 0;
    for (int iter = 0; iter < n; iter++) {
        bool k0, k1;
        {
            bool sup = false;
            if (ab0 >= 0) {
                unsigned long long kw = ((unsigned long long)s_kept[ab0 * 2 + 1] << 32)
                                        | (unsigned long long)s_kept[ab0 * 2];
                sup = (A0 & kw) != 0ULL;
            }
            if (!sup && ab1 >= 0) {
                unsigned long long kw = ((unsigned long long)s_kept[ab1 * 2 + 1] << 32)
                                        | (unsigned long long)s_kept[ab1 * 2];
                sup = (A1 & kw) != 0ULL;
            }
            unsigned s = rest0;
            while (!sup && s) {
                int blk = __ffs(s) - 1; s &= s - 1;
                unsigned long long m = g_maskT[(size_t)j0 * CB + blk];
                unsigned long long kw = ((unsigned long long)s_kept[blk * 2 + 1] << 32)
                                        | (unsigned long long)s_kept[blk * 2];
                sup = (m & kw) != 0ULL;
            }
            k0 = (j0 < n) && !sup;
        }
        {
            bool sup = false;
            if (bb0 >= 0) {
                unsigned long long kw = ((unsigned long long)s_kept[bb0 * 2 + 1] << 32)
                                        | (unsigned long long)s_kept[bb0 * 2];
                sup = (B0 & kw) != 0ULL;
            }
            if (!sup && bb1 >= 0) {
                unsigned long long kw = ((unsigned long long)s_kept[bb1 * 2 + 1] << 32)
                                        | (unsigned long long)s_kept[bb1 * 2];
                sup = (B1 & kw) != 0ULL;
            }
            unsigned s = rest1;
            while (!sup && s) {
                int blk = __ffs(s) - 1; s &= s - 1;
                unsigned long long m = g_maskT[(size_t)j1 * CB + blk];
                unsigned long long kw = ((unsigned long long)s_kept[blk * 2 + 1] << 32)
                                        | (unsigned long long)s_kept[blk * 2];
                sup = (m & kw) != 0ULL;
            }
            k1 = (j1 < n) && !sup;
        }
        __syncthreads();   // all reads of s_kept done
        unsigned b0 = __ballot_sync(FULLM, k0);
        unsigned b1 = __ballot_sync(FULLM, k1);
        int w = tid >> 5;
        if ((tid & 31) == 0) {
            if (s_kept[w] != b0)      { s_kept[w] = b0;      s_changed[cur] = 1; }
            if (s_kept[32 + w] != b1) { s_kept[32 + w] = b1; s_changed[cur] = 1; }
        }
        if (tid == 0) s_changed[cur ^ 1] = 0;   // pre-clear next flag
        __syncthreads();   // writes visible
        if (!s_changed[cur]) break;
        cur ^= 1;
    }

    // ---- emit ----
    if (tid == 0) {
        int acc = 0;
        for (int w = 0; w < 64; w++) { s_pref[w] = acc; acc += __popc(s_kept[w]); }
        s_total = acc;
    }
    __syncthreads();
    const int total = s_total;

#pragma unroll
    for (int rr = 0; rr < 2; rr++) {
        int j = tid + rr * RTPB;
        if (j < n) {
            unsigned w = s_kept[j >> 5];
            if ((w >> (j & 31)) & 1u) {
                int rank = (int)s_pref[j >> 5] + __popc(w & ((1u << (j & 31)) - 1u));
                if (rank < out_size) out[rank] = (float)j;
            }
        }
    }
    for (int k = total + tid; k < out_size; k += RTPB) out[k] = -1.0f;

    // ---- epilogue: restore scratch state to zero for next replay ----
    {
        unsigned s = cs0;
        while (s) { int blk = __ffs(s) - 1; s &= s - 1;
                    g_maskT[(size_t)j0 * CB + blk] = 0ULL; }
        if (j0 < n) g_colsum[j0] = 0u;
        s = cs1;
        while (s) { int blk = __ffs(s) - 1; s &= s - 1;
                    g_maskT[(size_t)j1 * CB + blk] = 0ULL; }
        if (j1 < n) g_colsum[j1] = 0u;
    }
}

// ---------------------------------------------------------------------------
extern "C" void kernel_launch(void* const* d_in, const int* in_sizes, int n_in,
                              void* d_out, int out_size) {
    const float* boxes = (const float*)d_in[0];
    int n = in_sizes[0] / 5;

    int rb = (n + TPB - 1) / TPB;  // 32 for n=2000
    dim3 grid(rb, rb);
    filter_kernel<<<grid, TPB>>>(boxes, n);

    clip_kernel<<<592, 128>>>(boxes);

    reduce_kernel<<<1, RTPB>>>(n, (float*)d_out, out_size);
}